// round 3
// baseline (speedup 1.0000x reference)
#include <cuda_runtime.h>
#include <math.h>

// SE(3) exp + point transform, split into:
//   A) compute_rt_kernel: per (b,t) compute R (row-major, 9) and t (3) -> g_RT
//   B) se3_transform_kernel: pure streaming  out = R*X + t
//
// X_v: [B,T,N,3] f32, dofs: [B,T,6] f32, out: [B,T,N,3] f32. B=64,T=28,N=4096.

#define THREADS 256
#define PTS_PER_THREAD 4       // 4 points = 12 floats = 3 float4
#define MAX_BT 8192

// scratch: 3 float4 per bt:  [r00 r01 r02 r10] [r11 r12 r20 r21] [r22 t0 t1 t2]
__device__ float4 g_RT[MAX_BT * 3];

__global__ void compute_rt_kernel(const float* __restrict__ dofs, int nBT)
{
    const int bt = blockIdx.x * blockDim.x + threadIdx.x;
    if (bt >= nBT) return;

    const float* d = dofs + bt * 6;
    const float tx = d[0], ty = d[1], tz = d[2];
    const float wx = d[3], wy = d[4], wz = d[5];

    const float nrm   = wx*wx + wy*wy + wz*wz;
    const float th2c  = fmaxf(nrm, 1.0e-4f);   // clip BEFORE sqrt (matches ref)
    const float theta = sqrtf(th2c);
    float st, ct;
    sincosf(theta, &st, &ct);
    const float f1 = st / theta;
    const float f2 = (1.0f - ct) / (theta * theta);
    const float f3 = (theta - st) / (theta * theta * theta);

    // H2 = H@H = w w^T - (w.w) I  (raw nrm, matches ref)
    const float h2xx = wx*wx - nrm, h2yy = wy*wy - nrm, h2zz = wz*wz - nrm;
    const float h2xy = wx*wy, h2xz = wx*wz, h2yz = wy*wz;

    const float r00 = 1.0f + f2*h2xx;
    const float r01 = -f1*wz + f2*h2xy;
    const float r02 =  f1*wy + f2*h2xz;
    const float r10 =  f1*wz + f2*h2xy;
    const float r11 = 1.0f + f2*h2yy;
    const float r12 = -f1*wx + f2*h2yz;
    const float r20 = -f1*wy + f2*h2xz;
    const float r21 =  f1*wx + f2*h2yz;
    const float r22 = 1.0f + f2*h2zz;

    const float v00 = 1.0f + f3*h2xx;
    const float v01 = -f2*wz + f3*h2xy;
    const float v02 =  f2*wy + f3*h2xz;
    const float v10 =  f2*wz + f3*h2xy;
    const float v11 = 1.0f + f3*h2yy;
    const float v12 = -f2*wx + f3*h2yz;
    const float v20 = -f2*wy + f3*h2xz;
    const float v21 =  f2*wx + f3*h2yz;
    const float v22 = 1.0f + f3*h2zz;

    const float t0 = v00*tx + v01*ty + v02*tz;
    const float t1 = v10*tx + v11*ty + v12*tz;
    const float t2 = v20*tx + v21*ty + v22*tz;

    g_RT[bt*3 + 0] = make_float4(r00, r01, r02, r10);
    g_RT[bt*3 + 1] = make_float4(r11, r12, r20, r21);
    g_RT[bt*3 + 2] = make_float4(r22, t0, t1, t2);
}

__global__ void __launch_bounds__(THREADS)
se3_transform_kernel(const float* __restrict__ X,
                     float* __restrict__ out,
                     int N)
{
    const int bt = blockIdx.y;

    const int ptBase = (blockIdx.x * THREADS + threadIdx.x) * PTS_PER_THREAD;
    if (ptBase >= N) return;

    const size_t base = (size_t)bt * (size_t)N * 3 + (size_t)ptBase * 3;
    const float4* __restrict__ src = reinterpret_cast<const float4*>(X + base);
    float4* __restrict__ dst = reinterpret_cast<float4*>(out + base);

    // Issue all 6 independent loads up front (MLP=6, no barrier).
    const float4 rt0 = __ldg(&g_RT[bt*3 + 0]);
    const float4 rt1 = __ldg(&g_RT[bt*3 + 1]);
    const float4 rt2 = __ldg(&g_RT[bt*3 + 2]);
    const float4 a = __ldcs(&src[0]);   // x0 y0 z0 x1
    const float4 b = __ldcs(&src[1]);   // y1 z1 x2 y2
    const float4 c = __ldcs(&src[2]);   // z2 x3 y3 z3

    const float r00 = rt0.x, r01 = rt0.y, r02 = rt0.z;
    const float r10 = rt0.w, r11 = rt1.x, r12 = rt1.y;
    const float r20 = rt1.z, r21 = rt1.w, r22 = rt2.x;
    const float t0  = rt2.y, t1  = rt2.z, t2  = rt2.w;

    const float o0x = fmaf(r00, a.x, fmaf(r01, a.y, fmaf(r02, a.z, t0)));
    const float o0y = fmaf(r10, a.x, fmaf(r11, a.y, fmaf(r12, a.z, t1)));
    const float o0z = fmaf(r20, a.x, fmaf(r21, a.y, fmaf(r22, a.z, t2)));

    const float o1x = fmaf(r00, a.w, fmaf(r01, b.x, fmaf(r02, b.y, t0)));
    const float o1y = fmaf(r10, a.w, fmaf(r11, b.x, fmaf(r12, b.y, t1)));
    const float o1z = fmaf(r20, a.w, fmaf(r21, b.x, fmaf(r22, b.y, t2)));

    const float o2x = fmaf(r00, b.z, fmaf(r01, b.w, fmaf(r02, c.x, t0)));
    const float o2y = fmaf(r10, b.z, fmaf(r11, b.w, fmaf(r12, c.x, t1)));
    const float o2z = fmaf(r20, b.z, fmaf(r21, b.w, fmaf(r22, c.x, t2)));

    const float o3x = fmaf(r00, c.y, fmaf(r01, c.z, fmaf(r02, c.w, t0)));
    const float o3y = fmaf(r10, c.y, fmaf(r11, c.z, fmaf(r12, c.w, t1)));
    const float o3z = fmaf(r20, c.y, fmaf(r21, c.z, fmaf(r22, c.w, t2)));

    __stcs(&dst[0], make_float4(o0x, o0y, o0z, o1x));
    __stcs(&dst[1], make_float4(o1y, o1z, o2x, o2y));
    __stcs(&dst[2], make_float4(o2z, o3x, o3y, o3z));
}

extern "C" void kernel_launch(void* const* d_in, const int* in_sizes, int n_in,
                              void* d_out, int out_size)
{
    const float* X    = (const float*)d_in[0];   // [B,T,N,3]
    const float* dofs = (const float*)d_in[1];   // [B,T,6]

    const int nBT = in_sizes[1] / 6;             // 1792
    const int N   = (in_sizes[0] / nBT) / 3;     // 4096

    compute_rt_kernel<<<(nBT + 255) / 256, 256>>>(dofs, nBT);

    const int ptsPerBlock = THREADS * PTS_PER_THREAD;        // 1024
    const int blocksX = (N + ptsPerBlock - 1) / ptsPerBlock; // 4
    dim3 grid(blocksX, nBT);
    se3_transform_kernel<<<grid, THREADS>>>(X, (float*)d_out, N);
}